// round 11
// baseline (speedup 1.0000x reference)
#include <cuda_runtime.h>
#include <cstdint>

#define H        128
#define TE       128
#define THREADS  128
#define GRID_P   296

// Aggregation scratch (allocation-free rule: __device__ globals)
__device__ float g_sum[65536];
__device__ float g_cnt[65536];

// SMEM word (u32/float) offsets — no activation buffer at all
#define OFF_WF0  0            // fp16 frag-major W0 (1 kc):  1024
#define OFF_WF1  1024         // fp16 frag-major W1 (8 kc):  8192
#define OFF_WF2  9216         // fp16 frag-major W2 (8 kc):  8192
#define OFF_B0   17408
#define OFF_B1   17536
#define OFF_B2   17664
#define OFF_W3   17792
#define OFF_B3   17920
#define OFF_FEAT 17924        // 128 edges x 4 feats = 512 floats
#define SMEM_WORDS 18436      // ~72 KB

__device__ __forceinline__ uint32_t pk16(float lo, float hi) {
    uint32_t u;
    asm("cvt.rn.f16x2.f32 %0, %1, %2;" : "=r"(u) : "f"(hi), "f"(lo));
    return u;
}

__device__ __forceinline__ void mma16(float* d, const uint32_t* a,
                                      uint32_t b0, uint32_t b1) {
    asm volatile("mma.sync.aligned.m16n8k16.row.col.f32.f16.f16.f32 "
        "{%0,%1,%2,%3}, {%4,%5,%6,%7}, {%8,%9}, {%0,%1,%2,%3};"
        : "+f"(d[0]), "+f"(d[1]), "+f"(d[2]), "+f"(d[3])
        : "r"(a[0]), "r"(a[1]), "r"(a[2]), "r"(a[3]), "r"(b0), "r"(b1));
}

// Stage W[K][H] (row-major, fp32) into fp16 B-fragment-major (proven map):
// WFu[((kc*8 + ncp)*32 + lane)*4 + r]
__device__ void stage_w(const float* __restrict__ W, int KC16, int Kreal,
                        uint32_t* __restrict__ WF, int tid) {
    int total = KC16 * 1024;
    for (int idx = tid; idx < total; idx += THREADS) {
        int r    = idx & 3;
        int lane = (idx >> 2) & 31;
        int ncp  = (idx >> 7) & 7;
        int kc   = idx >> 10;
        int c = lane & 3, g = lane >> 2;
        int n = (2 * ncp + (r >> 1)) * 8 + g;
        int kb = kc * 16 + 2 * c + ((r & 1) << 3);
        float lo = (kb     < Kreal) ? W[kb * H + n]       : 0.0f;
        float hi = (kb + 1 < Kreal) ? W[(kb + 1) * H + n] : 0.0f;
        WF[idx] = pk16(lo, hi);
    }
}

// Layer with A in registers. Warp tile m=32 (mc 0..1) x n=128 (nc 0..15).
template<int KC16>
__device__ __forceinline__ void layer_reg(const uint32_t* __restrict__ smu,
                                          int wfOff, int lane,
                                          const uint32_t A[2][8][4],
                                          float acc[2][16][4]) {
    #pragma unroll
    for (int mc = 0; mc < 2; mc++)
        #pragma unroll
        for (int nc = 0; nc < 16; nc++)
            #pragma unroll
            for (int i = 0; i < 4; i++) acc[mc][nc][i] = 0.0f;

    const uint4* wf = (const uint4*)(smu + wfOff);
    #pragma unroll
    for (int kc = 0; kc < KC16; kc++) {
        #pragma unroll
        for (int ncp = 0; ncp < 8; ncp++) {
            uint4 bv = wf[(kc * 8 + ncp) * 32 + lane];
            #pragma unroll
            for (int mc = 0; mc < 2; mc++) {
                mma16(acc[mc][2 * ncp],     A[mc][kc], bv.x, bv.y);
                mma16(acc[mc][2 * ncp + 1], A[mc][kc], bv.z, bv.w);
            }
        }
    }
}

// acc (+bias, relu) -> fp16 A fragments for the next layer. Pure lane-local.
__device__ __forceinline__ void pack_A(const float acc[2][16][4],
                                       const float* __restrict__ bias,
                                       int q, uint32_t A[2][8][4]) {
    #pragma unroll
    for (int kc = 0; kc < 8; kc++) {
        float2 bA = *(const float2*)(bias + 16 * kc + 2 * q);
        float2 bB = *(const float2*)(bias + 16 * kc + 8 + 2 * q);
        #pragma unroll
        for (int mc = 0; mc < 2; mc++) {
            A[mc][kc][0] = pk16(fmaxf(acc[mc][2 * kc][0] + bA.x, 0.f),
                                fmaxf(acc[mc][2 * kc][1] + bA.y, 0.f));
            A[mc][kc][1] = pk16(fmaxf(acc[mc][2 * kc][2] + bA.x, 0.f),
                                fmaxf(acc[mc][2 * kc][3] + bA.y, 0.f));
            A[mc][kc][2] = pk16(fmaxf(acc[mc][2 * kc + 1][0] + bB.x, 0.f),
                                fmaxf(acc[mc][2 * kc + 1][1] + bB.y, 0.f));
            A[mc][kc][3] = pk16(fmaxf(acc[mc][2 * kc + 1][2] + bB.x, 0.f),
                                fmaxf(acc[mc][2 * kc + 1][3] + bB.y, 0.f));
        }
    }
}

// ---------------------------------------------------------------------------
__global__ void node_kernel(const float* __restrict__ theta,
                            const float* __restrict__ v0p,
                            float* __restrict__ out, int N) {
    int i = blockIdx.x * blockDim.x + threadIdx.x;
    if (i < N) {
        float s, c;
        sincosf(theta[i], &s, &c);
        float v0 = *v0p;
        out[2 * i + 0] = v0 * c;
        out[2 * i + 1] = v0 * s;
        g_sum[i] = 0.0f;
        g_cnt[i] = 0.0f;
    }
}

// ---------------------------------------------------------------------------
__global__ __launch_bounds__(THREADS, 2)
void edge_kernel(const float* __restrict__ x, const float* __restrict__ theta,
                 const float* __restrict__ W0, const float* __restrict__ b0,
                 const float* __restrict__ W1, const float* __restrict__ b1,
                 const float* __restrict__ W2, const float* __restrict__ b2,
                 const float* __restrict__ W3, const float* __restrict__ b3,
                 const int* __restrict__ src, const int* __restrict__ dst,
                 int E, int nTiles) {
    extern __shared__ __align__(16) uint32_t smu[];
    float* smf = (float*)smu;
    const int tid  = threadIdx.x;
    const int wid  = tid >> 5;
    const int lane = tid & 31;
    const int r    = lane >> 2;
    const int q    = lane & 3;
    const int m0   = wid * 32;

    // ---- stage weights once per CTA ----
    stage_w(W0, 1, 4,   smu + OFF_WF0, tid);
    stage_w(W1, 8, 128, smu + OFF_WF1, tid);
    stage_w(W2, 8, 128, smu + OFF_WF2, tid);
    if (tid < H) {
        smf[OFF_B0 + tid] = b0[tid];
        smf[OFF_B1 + tid] = b1[tid];
        smf[OFF_B2 + tid] = b2[tid];
        smf[OFF_W3 + tid] = W3[tid];
    }
    if (tid == 0) smf[OFF_B3] = b3[0];
    __syncthreads();

    uint32_t A[2][8][4];
    float acc[2][16][4];

    for (int tile = blockIdx.x; tile < nTiles; tile += gridDim.x) {
        const int ebase = tile * TE;

        // ---- features -> tiny smem staging; count atomics here ----
        {
            int e = ebase + tid;
            float f0 = 0.f, f1 = 0.f, f2 = 0.f, f3 = 0.f;
            if (e < E) {
                int is = src[e], id = dst[e];
                float xs = x[2 * is], ys = x[2 * is + 1];
                float xd = x[2 * id], yd = x[2 * id + 1];
                float ths = theta[is], thd = theta[id];
                float sn, cn; sincosf(thd - ths, &sn, &cn);
                float s0, c0; sincosf(ths, &s0, &c0);
                float drx = xd - xs, dry = yd - ys;
                f0 =  drx * c0 + dry * s0;
                f1 = -drx * s0 + dry * c0;
                f2 = cn; f3 = sn;
                atomicAdd(&g_cnt[id], 1.0f);
            }
            float4* fp = (float4*)(smf + OFF_FEAT);
            fp[tid] = make_float4(f0, f1, f2, f3);
        }
        __syncthreads();

        // ---- build A0 from features (only q<2 nonzero; k>=4 is zero) ----
        #pragma unroll
        for (int mc = 0; mc < 2; mc++)
            #pragma unroll
            for (int kc = 0; kc < 8; kc++)
                #pragma unroll
                for (int i = 0; i < 4; i++) A[mc][kc][i] = 0u;
        if (q < 2) {
            #pragma unroll
            for (int mc = 0; mc < 2; mc++) {
                int row = m0 + 16 * mc + r;
                const float* fr0 = smf + OFF_FEAT + row * 4;
                const float* fr1 = smf + OFF_FEAT + (row + 8) * 4;
                A[mc][0][0] = pk16(fr0[2 * q], fr0[2 * q + 1]);
                A[mc][0][1] = pk16(fr1[2 * q], fr1[2 * q + 1]);
            }
        }

        // ---- register-resident MLP chain: no barriers between layers ----
        layer_reg<1>(smu, OFF_WF0, lane, A, acc);
        pack_A(acc, smf + OFF_B0, q, A);
        layer_reg<8>(smu, OFF_WF1, lane, A, acc);
        pack_A(acc, smf + OFF_B1, q, A);
        layer_reg<8>(smu, OFF_WF2, lane, A, acc);

        // ---- fused final dot: h2 never leaves registers ----
        {
            float p[4] = {0.f, 0.f, 0.f, 0.f};   // rows m0+16mc+r, +8
            #pragma unroll
            for (int nc = 0; nc < 16; nc++) {
                int col = 8 * nc + 2 * q;
                float2 bb = *(const float2*)(smf + OFF_B2 + col);
                float2 w3 = *(const float2*)(smf + OFF_W3 + col);
                #pragma unroll
                for (int mc = 0; mc < 2; mc++) {
                    p[2 * mc]     += fmaxf(acc[mc][nc][0] + bb.x, 0.f) * w3.x
                                   + fmaxf(acc[mc][nc][1] + bb.y, 0.f) * w3.y;
                    p[2 * mc + 1] += fmaxf(acc[mc][nc][2] + bb.x, 0.f) * w3.x
                                   + fmaxf(acc[mc][nc][3] + bb.y, 0.f) * w3.y;
                }
            }
            #pragma unroll
            for (int i = 0; i < 4; i++) {
                p[i] += __shfl_xor_sync(0xffffffffu, p[i], 1);
                p[i] += __shfl_xor_sync(0xffffffffu, p[i], 2);
            }
            if (q == 0) {
                float bb3 = smf[OFF_B3];
                #pragma unroll
                for (int i = 0; i < 4; i++) {
                    int row = m0 + 16 * (i >> 1) + r + 8 * (i & 1);
                    int e = ebase + row;
                    if (e < E) atomicAdd(&g_sum[dst[e]], p[i] + bb3);
                }
            }
        }
        __syncthreads();   // feat staging reads done before next tile's write
    }
}

// ---------------------------------------------------------------------------
__global__ void torque_kernel(float* __restrict__ out, int N) {
    int i = blockIdx.x * blockDim.x + threadIdx.x;
    if (i < N) out[2 * N + i] = g_sum[i] / fmaxf(g_cnt[i], 1.0f);
}

// ---------------------------------------------------------------------------
extern "C" void kernel_launch(void* const* d_in, const int* in_sizes, int n_in,
                              void* d_out, int out_size) {
    const float* x     = (const float*)d_in[0];
    const float* theta = (const float*)d_in[1];
    const float* v0    = (const float*)d_in[2];
    const float* W0    = (const float*)d_in[3];
    const float* b0    = (const float*)d_in[4];
    const float* W1    = (const float*)d_in[5];
    const float* b1    = (const float*)d_in[6];
    const float* W2    = (const float*)d_in[7];
    const float* b2    = (const float*)d_in[8];
    const float* W3    = (const float*)d_in[9];
    const float* b3    = (const float*)d_in[10];
    const int*   src   = (const int*)d_in[11];
    const int*   dst   = (const int*)d_in[12];

    int N = in_sizes[1];
    int E = in_sizes[11];
    int nTiles = (E + TE - 1) / TE;
    float* out = (float*)d_out;

    size_t smem = (size_t)SMEM_WORDS * sizeof(uint32_t);
    cudaFuncSetAttribute(edge_kernel,
                         cudaFuncAttributeMaxDynamicSharedMemorySize, (int)smem);

    int grid = GRID_P;
    if (nTiles < grid) grid = nTiles;

    node_kernel<<<(N + 255) / 256, 256>>>(theta, v0, out, N);
    edge_kernel<<<grid, THREADS, smem>>>(
        x, theta, W0, b0, W1, b1, W2, b2, W3, b3, src, dst, E, nTiles);
    torque_kernel<<<(N + 255) / 256, 256>>>(out, N);
}

// round 12
// speedup vs baseline: 1.1191x; 1.1191x over previous
#include <cuda_runtime.h>
#include <cstdint>

#define H        128
#define TE       128
#define THREADS  128
#define GRID_P   296          // 2 CTAs/SM guaranteed by launch_bounds+smem -> barrier safe

// Aggregation scratch + barrier state (allocation-free rule: __device__ globals)
__device__ float g_sum[65536];
__device__ float g_cnt[65536];
__device__ unsigned g_barcnt = 0;
__device__ volatile unsigned g_sense = 0;

// SMEM word (u32/float) offsets — no activation buffer
#define OFF_WF0  0            // fp16 frag-major W0 (1 kc):  1024
#define OFF_WF1  1024         // fp16 frag-major W1 (8 kc):  8192
#define OFF_WF2  9216         // fp16 frag-major W2 (8 kc):  8192
#define OFF_B0   17408
#define OFF_B1   17536
#define OFF_B2   17664
#define OFF_W3   17792
#define OFF_B3   17920
#define OFF_FEAT 17924        // double-buffered: 2 x 128 edges x 4 = 1024 floats
#define SMEM_WORDS 18948      // ~74 KB -> 2 CTAs/SM

__device__ __forceinline__ uint32_t pk16(float lo, float hi) {
    uint32_t u;
    asm("cvt.rn.f16x2.f32 %0, %1, %2;" : "=r"(u) : "f"(hi), "f"(lo));
    return u;
}

__device__ __forceinline__ void mma16(float* d, const uint32_t* a,
                                      uint32_t b0, uint32_t b1) {
    asm volatile("mma.sync.aligned.m16n8k16.row.col.f32.f16.f16.f32 "
        "{%0,%1,%2,%3}, {%4,%5,%6,%7}, {%8,%9}, {%0,%1,%2,%3};"
        : "+f"(d[0]), "+f"(d[1]), "+f"(d[2]), "+f"(d[3])
        : "r"(a[0]), "r"(a[1]), "r"(a[2]), "r"(a[3]), "r"(b0), "r"(b1));
}

// k=8 fp16 MMA for layer0 (k pad eliminated): A {a0,a1}, B {b0}
__device__ __forceinline__ void mma8(float* d, uint32_t a0, uint32_t a1,
                                     uint32_t b0) {
    asm volatile("mma.sync.aligned.m16n8k8.row.col.f32.f16.f16.f32 "
        "{%0,%1,%2,%3}, {%4,%5}, {%6}, {%0,%1,%2,%3};"
        : "+f"(d[0]), "+f"(d[1]), "+f"(d[2]), "+f"(d[3])
        : "r"(a0), "r"(a1), "r"(b0));
}

// Sense-reversing grid barrier. Safe: 2 CTAs/SM residency is guaranteed
// (regs capped by launch_bounds, smem 74KB*2 < 228KB), grid = 296 = 2*148.
__device__ __forceinline__ void grid_bar() {
    __syncthreads();
    if (threadIdx.x == 0) {
        unsigned s = g_sense;
        __threadfence();
        if (atomicAdd(&g_barcnt, 1u) == gridDim.x - 1) {
            g_barcnt = 0;
            __threadfence();
            g_sense = s ^ 1u;
        } else {
            while (g_sense == s) { }
        }
        __threadfence();
    }
    __syncthreads();
}

// Stage W[K][H] (row-major, fp32) into fp16 B-fragment-major (proven map):
// WFu[((kc*8 + ncp)*32 + lane)*4 + r]
__device__ void stage_w(const float* __restrict__ W, int KC16, int Kreal,
                        uint32_t* __restrict__ WF, int tid) {
    int total = KC16 * 1024;
    for (int idx = tid; idx < total; idx += THREADS) {
        int r    = idx & 3;
        int lane = (idx >> 2) & 31;
        int ncp  = (idx >> 7) & 7;
        int kc   = idx >> 10;
        int c = lane & 3, g = lane >> 2;
        int n = (2 * ncp + (r >> 1)) * 8 + g;
        int kb = kc * 16 + 2 * c + ((r & 1) << 3);
        float lo = (kb     < Kreal) ? W[kb * H + n]       : 0.0f;
        float hi = (kb + 1 < Kreal) ? W[(kb + 1) * H + n] : 0.0f;
        WF[idx] = pk16(lo, hi);
    }
}

// Heavy layer, A in registers. Warp tile m=32 (mc 0..1) x n=128 (nc 0..15).
__device__ __forceinline__ void layer_reg(const uint32_t* __restrict__ smu,
                                          int wfOff, int lane,
                                          const uint32_t A[2][8][4],
                                          float acc[2][16][4]) {
    #pragma unroll
    for (int mc = 0; mc < 2; mc++)
        #pragma unroll
        for (int nc = 0; nc < 16; nc++)
            #pragma unroll
            for (int i = 0; i < 4; i++) acc[mc][nc][i] = 0.0f;

    const uint4* wf = (const uint4*)(smu + wfOff);
    #pragma unroll
    for (int kc = 0; kc < 8; kc++) {
        #pragma unroll
        for (int ncp = 0; ncp < 8; ncp++) {
            uint4 bv = wf[(kc * 8 + ncp) * 32 + lane];
            #pragma unroll
            for (int mc = 0; mc < 2; mc++) {
                mma16(acc[mc][2 * ncp],     A[mc][kc], bv.x, bv.y);
                mma16(acc[mc][2 * ncp + 1], A[mc][kc], bv.z, bv.w);
            }
        }
    }
}

// acc (+bias, relu) -> fp16 A fragments for the next layer. Pure lane-local.
__device__ __forceinline__ void pack_A(const float acc[2][16][4],
                                       const float* __restrict__ bias,
                                       int q, uint32_t A[2][8][4]) {
    #pragma unroll
    for (int kc = 0; kc < 8; kc++) {
        float2 bA = *(const float2*)(bias + 16 * kc + 2 * q);
        float2 bB = *(const float2*)(bias + 16 * kc + 8 + 2 * q);
        #pragma unroll
        for (int mc = 0; mc < 2; mc++) {
            A[mc][kc][0] = pk16(fmaxf(acc[mc][2 * kc][0] + bA.x, 0.f),
                                fmaxf(acc[mc][2 * kc][1] + bA.y, 0.f));
            A[mc][kc][1] = pk16(fmaxf(acc[mc][2 * kc][2] + bA.x, 0.f),
                                fmaxf(acc[mc][2 * kc][3] + bA.y, 0.f));
            A[mc][kc][2] = pk16(fmaxf(acc[mc][2 * kc + 1][0] + bB.x, 0.f),
                                fmaxf(acc[mc][2 * kc + 1][1] + bB.y, 0.f));
            A[mc][kc][3] = pk16(fmaxf(acc[mc][2 * kc + 1][2] + bB.x, 0.f),
                                fmaxf(acc[mc][2 * kc + 1][3] + bB.y, 0.f));
        }
    }
}

// ---------------------------------------------------------------------------
// Single persistent kernel: velocity+zero | bar | edge tiles | bar | torque
// ---------------------------------------------------------------------------
__global__ __launch_bounds__(THREADS, 2)
void fused_kernel(const float* __restrict__ x, const float* __restrict__ theta,
                  const float* __restrict__ v0p,
                  const float* __restrict__ W0, const float* __restrict__ b0,
                  const float* __restrict__ W1, const float* __restrict__ b1,
                  const float* __restrict__ W2, const float* __restrict__ b2,
                  const float* __restrict__ W3, const float* __restrict__ b3,
                  const int* __restrict__ src, const int* __restrict__ dst,
                  float* __restrict__ out, int N, int E, int nTiles) {
    extern __shared__ __align__(16) uint32_t smu[];
    float* smf = (float*)smu;
    const int tid  = threadIdx.x;
    const int wid  = tid >> 5;
    const int lane = tid & 31;
    const int r    = lane >> 2;
    const int q    = lane & 3;
    const int m0   = wid * 32;

    // ---- phase A: velocity + zero aggregation scratch ----
    {
        float v0 = *v0p;
        for (int i = blockIdx.x * THREADS + tid; i < N; i += gridDim.x * THREADS) {
            float s, c;
            sincosf(theta[i], &s, &c);
            out[2 * i + 0] = v0 * c;
            out[2 * i + 1] = v0 * s;
            g_sum[i] = 0.0f;
            g_cnt[i] = 0.0f;
        }
    }

    // ---- stage weights once per CTA ----
    stage_w(W0, 1, 4,   smu + OFF_WF0, tid);
    stage_w(W1, 8, 128, smu + OFF_WF1, tid);
    stage_w(W2, 8, 128, smu + OFF_WF2, tid);
    if (tid < H) {
        smf[OFF_B0 + tid] = b0[tid];
        smf[OFF_B1 + tid] = b1[tid];
        smf[OFF_B2 + tid] = b2[tid];
        smf[OFF_W3 + tid] = W3[tid];
    }
    if (tid == 0) smf[OFF_B3] = b3[0];

    grid_bar();   // zeroing complete everywhere before any atomics

    uint32_t A[2][8][4];
    float acc[2][16][4];
    int fb = 0;   // feature double-buffer selector

    for (int tile = blockIdx.x; tile < nTiles; tile += gridDim.x) {
        const int ebase = tile * TE;
        float* feat = smf + OFF_FEAT + fb * 512;

        // ---- features -> staged buffer fb; count atomics here ----
        {
            int e = ebase + tid;
            float f0 = 0.f, f1 = 0.f, f2 = 0.f, f3 = 0.f;
            if (e < E) {
                int is = src[e], id = dst[e];
                float xs = x[2 * is], ys = x[2 * is + 1];
                float xd = x[2 * id], yd = x[2 * id + 1];
                float ths = theta[is], thd = theta[id];
                float sn, cn; sincosf(thd - ths, &sn, &cn);
                float s0, c0; sincosf(ths, &s0, &c0);
                float drx = xd - xs, dry = yd - ys;
                f0 =  drx * c0 + dry * s0;
                f1 = -drx * s0 + dry * c0;
                f2 = cn; f3 = sn;
                atomicAdd(&g_cnt[id], 1.0f);
            }
            ((float4*)feat)[tid] = make_float4(f0, f1, f2, f3);
        }
        __syncthreads();   // the ONLY per-tile barrier (feat dbl-buffered)

        // ---- A0 feature fragments (k=0..7: q<2 real, rest zero) ----
        uint32_t a00[2], a01[2];
        #pragma unroll
        for (int mc = 0; mc < 2; mc++) {
            if (q < 2) {
                int row = m0 + 16 * mc + r;
                a00[mc] = pk16(feat[row * 4 + 2 * q], feat[row * 4 + 2 * q + 1]);
                a01[mc] = pk16(feat[(row + 8) * 4 + 2 * q], feat[(row + 8) * 4 + 2 * q + 1]);
            } else {
                a00[mc] = 0u; a01[mc] = 0u;
            }
        }

        // ---- layer 0: k=8 MMAs (pad half dropped) ----
        {
            #pragma unroll
            for (int mc = 0; mc < 2; mc++)
                #pragma unroll
                for (int nc = 0; nc < 16; nc++)
                    #pragma unroll
                    for (int i = 0; i < 4; i++) acc[mc][nc][i] = 0.0f;
            const uint4* wf = (const uint4*)(smu + OFF_WF0);
            #pragma unroll
            for (int ncp = 0; ncp < 8; ncp++) {
                uint4 bv = wf[ncp * 32 + lane];   // .x = b0 even chunk, .z = b0 odd
                #pragma unroll
                for (int mc = 0; mc < 2; mc++) {
                    mma8(acc[mc][2 * ncp],     a00[mc], a01[mc], bv.x);
                    mma8(acc[mc][2 * ncp + 1], a00[mc], a01[mc], bv.z);
                }
            }
        }
        pack_A(acc, smf + OFF_B0, q, A);
        layer_reg(smu, OFF_WF1, lane, A, acc);
        pack_A(acc, smf + OFF_B1, q, A);
        layer_reg(smu, OFF_WF2, lane, A, acc);

        // ---- fused final dot: h2 never leaves registers ----
        {
            float p[4] = {0.f, 0.f, 0.f, 0.f};   // rows m0+16mc+r, +8
            #pragma unroll
            for (int nc = 0; nc < 16; nc++) {
                int col = 8 * nc + 2 * q;
                float2 bb = *(const float2*)(smf + OFF_B2 + col);
                float2 w3 = *(const float2*)(smf + OFF_W3 + col);
                #pragma unroll
                for (int mc = 0; mc < 2; mc++) {
                    p[2 * mc]     += fmaxf(acc[mc][nc][0] + bb.x, 0.f) * w3.x
                                   + fmaxf(acc[mc][nc][1] + bb.y, 0.f) * w3.y;
                    p[2 * mc + 1] += fmaxf(acc[mc][nc][2] + bb.x, 0.f) * w3.x
                                   + fmaxf(acc[mc][nc][3] + bb.y, 0.f) * w3.y;
                }
            }
            #pragma unroll
            for (int i = 0; i < 4; i++) {
                p[i] += __shfl_xor_sync(0xffffffffu, p[i], 1);
                p[i] += __shfl_xor_sync(0xffffffffu, p[i], 2);
            }
            if (q == 0) {
                float bb3 = smf[OFF_B3];
                #pragma unroll
                for (int i = 0; i < 4; i++) {
                    int row = m0 + 16 * (i >> 1) + r + 8 * (i & 1);
                    int e = ebase + row;
                    if (e < E) atomicAdd(&g_sum[dst[e]], p[i] + bb3);
                }
            }
        }
        fb ^= 1;   // no trailing barrier: next tile writes the other buffer
    }

    __threadfence();   // publish this CTA's atomics before the barrier
    grid_bar();

    // ---- phase C: torque = mean ----
    for (int i = blockIdx.x * THREADS + tid; i < N; i += gridDim.x * THREADS)
        out[2 * N + i] = g_sum[i] / fmaxf(g_cnt[i], 1.0f);
}

// ---------------------------------------------------------------------------
extern "C" void kernel_launch(void* const* d_in, const int* in_sizes, int n_in,
                              void* d_out, int out_size) {
    const float* x     = (const float*)d_in[0];
    const float* theta = (const float*)d_in[1];
    const float* v0    = (const float*)d_in[2];
    const float* W0    = (const float*)d_in[3];
    const float* b0    = (const float*)d_in[4];
    const float* W1    = (const float*)d_in[5];
    const float* b1    = (const float*)d_in[6];
    const float* W2    = (const float*)d_in[7];
    const float* b2    = (const float*)d_in[8];
    const float* W3    = (const float*)d_in[9];
    const float* b3    = (const float*)d_in[10];
    const int*   src   = (const int*)d_in[11];
    const int*   dst   = (const int*)d_in[12];

    int N = in_sizes[1];
    int E = in_sizes[11];
    int nTiles = (E + TE - 1) / TE;
    float* out = (float*)d_out;

    size_t smem = (size_t)SMEM_WORDS * sizeof(uint32_t);
    cudaFuncSetAttribute(fused_kernel,
                         cudaFuncAttributeMaxDynamicSharedMemorySize, (int)smem);

    fused_kernel<<<GRID_P, THREADS, smem>>>(
        x, theta, v0, W0, b0, W1, b1, W2, b2, W3, b3, src, dst,
        out, N, E, nTiles);
}